// round 17
// baseline (speedup 1.0000x reference)
#include <cuda_runtime.h>
#include <cuda_bf16.h>
#include <math.h>

// Problem constants
#define TT     1024
#define DD     4
#define PP     8
#define DPW    32                    // D*P
#define SS     256                   // N * N_SAMPLE
#define QTR    4                     // blocks per sample in P1/P3
#define NCH8   128                   // 8-step chunks per sample
#define TBL    (TT*DPW)              // 32768 table elements
#define SZ     ((size_t)SS*TT*DPW)   // 8388608 elements per output tensor
#define HLOG2PI 0.91893853320467274178f

// Scratch (static __device__ arrays — allocation-free)
__device__ float  g_mean[TBL];
__device__ float  g_sw[TBL];
__device__ float  g_amul[TT*DD];          // sigmoid(a_raw[t-1,d]), amul[0,*]=0
__device__ float  g_A8[NCH8*DD];          // per-8-chunk amul products (s-indep)
__device__ float4 g_B[SS*NCH8*8];         // per-8-chunk local end values, 4 MB

// ---------------------------------------------------------------------------
// K0: precompute per-(t,dp) tables. Fast-math; tiny.
// ---------------------------------------------------------------------------
__global__ void arma_precompute(const float* __restrict__ m,
                                const float* __restrict__ s_raw,
                                const float* __restrict__ a_raw,
                                const int*   __restrict__ dim_idx)
{
    int idx = blockIdx.x * blockDim.x + threadIdx.x;
    if (idx >= TBL) return;
    int t  = idx >> 5;
    int dp = idx & 31;
    int dd = dp >> 3;
    int p  = dp & 7;
    int src = dim_idx[dd];

    float am = 0.0f;
    if (t > 0) {
        float x = a_raw[(t - 1) * DD + src];
        am = 1.0f / (1.0f + __expf(-x));
    }

    float sv = s_raw[t * DPW + src * PP + p];
    float sw = (sv > 20.0f) ? sv : __logf(1.0f + __expf(sv));   // softplus
    float mn = (1.0f - am) * m[t * DPW + src * PP + p];

    g_mean[idx] = mn;
    g_sw[idx]   = sw;
    if (p == 0) g_amul[t * DD + dd] = am;
}

// ---------------------------------------------------------------------------
// K0b: per-8-chunk amul products (s-independent). 512 threads, trivial.
// ---------------------------------------------------------------------------
__global__ void arma_a8()
{
    int idx = threadIdx.x + blockIdx.x * blockDim.x;   // 0..511
    if (idx >= NCH8 * DD) return;
    int c  = idx >> 2;
    int dd = idx & 3;
    float a = 1.0f;
    int t0 = c << 3;
#pragma unroll
    for (int j = 0; j < 8; j++)
        a *= g_amul[((t0 + j) << 2) + dd];
    g_A8[idx] = a;
}

// ---------------------------------------------------------------------------
// P1: stream noise once (float4, DEFAULT policy so L2 retains it for P3),
// write lp (__stcs, never re-read), emit TWO 8-step summaries per 16-step
// thread-chunk (store at i=7, reset, store at end). LT=16 keeps 16
// independent float4 loads in flight (DRAM latency hiding).
// Grid: 1024 blocks (s, quarter) x 128 threads (16 chunks x 8 quads).
// ---------------------------------------------------------------------------
__global__ void __launch_bounds__(128)
arma_pass1(const float4* __restrict__ noise4,
           float4* __restrict__ lp4,
           int write_lp)
{
    const int s      = blockIdx.x >> 2;
    const int qt     = blockIdx.x & 3;
    const int q      = threadIdx.x & 7;                  // dp quad
    const int chunk16= (qt << 4) + (threadIdx.x >> 3);   // 0..63
    const int dd     = q >> 1;
    const int t0     = chunk16 << 4;

    const float4* tbl_sw = (const float4*)g_sw;
    const float4* tbl_mn = (const float4*)g_mean;

    const size_t base = ((size_t)((s << 10) + t0) << 3) + q;   // float4 index

    float4 b = make_float4(0.f, 0.f, 0.f, 0.f);

#pragma unroll
    for (int i = 0; i < 16; i++) {
        const int t  = t0 + i;
        const int ti = (t << 3) + q;
        const float4 n  = noise4[base + (size_t)i * 8];        // keep in L2
        const float4 sw = tbl_sw[ti];
        const float4 mn = tbl_mn[ti];
        if (write_lp) {
            float4 lp;
            lp.x = fmaf(-0.5f * n.x, n.x, -__logf(sw.x) - HLOG2PI);
            lp.y = fmaf(-0.5f * n.y, n.y, -__logf(sw.y) - HLOG2PI);
            lp.z = fmaf(-0.5f * n.z, n.z, -__logf(sw.z) - HLOG2PI);
            lp.w = fmaf(-0.5f * n.w, n.w, -__logf(sw.w) - HLOG2PI);
            __stcs(&lp4[base + (size_t)i * 8], lp);
        }
        const float am = g_amul[(t << 2) + dd];
        b.x = fmaf(am, b.x, fmaf(sw.x, n.x, mn.x));
        b.y = fmaf(am, b.y, fmaf(sw.y, n.y, mn.y));
        b.z = fmaf(am, b.z, fmaf(sw.z, n.z, mn.z));
        b.w = fmaf(am, b.w, fmaf(sw.w, n.w, mn.w));
        if (i == 7) {
            g_B[(((size_t)s << 7) + 2 * chunk16) * 8 + q] = b;  // even 8-chunk
            b = make_float4(0.f, 0.f, 0.f, 0.f);
        }
    }
    g_B[(((size_t)s << 7) + 2 * chunk16 + 1) * 8 + q] = b;      // odd 8-chunk
}

// ---------------------------------------------------------------------------
// P3 (scan folded, LT=8): grid 1024 (s, quarter) x 256 threads = 262144
// threads (~86% of chip thread slots — the configuration that ran this pass
// at 12.4us in R11).
// Prologue: load the sample's full B8 (16KB, L2-hot) + A8 (2KB); warp0 runs
// the 128-step fma carry chain in smem, keeping carries for this block's 32
// local 8-chunks. Main: replay 8 steps; noise re-read is an L2 hit.
// ---------------------------------------------------------------------------
__global__ void __launch_bounds__(256)
arma_pass2(const float4* __restrict__ noise4,
           float4* __restrict__ param4)
{
    const int s      = blockIdx.x >> 2;
    const int qt     = blockIdx.x & 3;
    const int tid    = threadIdx.x;
    const int q      = tid & 7;
    const int lchunk = tid >> 3;                         // 0..31 local 8-chunk
    const int chunk8 = (qt << 5) + lchunk;               // 0..127 global
    const int dd     = q >> 1;
    const int t0     = chunk8 << 3;

    __shared__ float sA[NCH8][DD];        // 2 KB   per-8-chunk amul products
    __shared__ float sB[NCH8][DPW];       // 16 KB  per-8-chunk local ends
    __shared__ float sC[32][DPW];         // 4 KB   carries for local chunks

    // Load A8 (128 float4) and B8 (1024 float4, 4 per thread)
    if (tid < 128)
        ((float4*)sA)[tid] = ((const float4*)g_A8)[tid];
    const float4* Bs = g_B + ((size_t)s << 7) * 8;
#pragma unroll
    for (int k = 0; k < 4; k++)
        ((float4*)sB)[tid + 256 * k] = Bs[tid + 256 * k];
    __syncthreads();

    // Warp0: serial affine scan over 128 8-chunks; keep this block's carries.
    if (tid < 32) {
        const int dp = tid;
        const int d2 = dp >> 3;
        const int lo = qt << 5;
        float carry = 0.0f;
#pragma unroll
        for (int c = 0; c < NCH8; c++) {
            if ((c >> 5) == qt) sC[c - lo][dp] = carry;
            carry = fmaf(sA[c][d2], carry, sB[c][dp]);
        }
    }
    __syncthreads();

    const float4* tbl_sw = (const float4*)g_sw;
    const float4* tbl_mn = (const float4*)g_mean;

    const size_t base = ((size_t)((s << 10) + t0) << 3) + q;

    float4 pv = ((const float4*)sC[lchunk])[q];

#pragma unroll
    for (int i = 0; i < 8; i++) {
        const int t  = t0 + i;
        const int ti = (t << 3) + q;
        const float4 n  = noise4[base + (size_t)i * 8];   // L2 hit (read in P1)
        const float4 sw = tbl_sw[ti];
        const float4 mn = tbl_mn[ti];
        const float am  = g_amul[(t << 2) + dd];
        pv.x = fmaf(am, pv.x, fmaf(sw.x, n.x, mn.x));
        pv.y = fmaf(am, pv.y, fmaf(sw.y, n.y, mn.y));
        pv.z = fmaf(am, pv.z, fmaf(sw.z, n.z, mn.z));
        pv.w = fmaf(am, pv.w, fmaf(sw.w, n.w, mn.w));
        __stcs(&param4[base + (size_t)i * 8], pv);
    }
}

// ---------------------------------------------------------------------------
// Launch.  Inputs: 0:y 1:age 2:m 3:s_raw 4:a_raw 5:noise 6:cond_sample
//                  7:dim_idx 8:compute_log_prob
// Output: param (S,T,D,P) then log_prob (S,T,D,P), float32.
// ---------------------------------------------------------------------------
extern "C" void kernel_launch(void* const* d_in, const int* in_sizes, int n_in,
                              void* d_out, int out_size)
{
    const float* m      = (const float*)d_in[2];
    const float* s_raw  = (const float*)d_in[3];
    const float* a_raw  = (const float*)d_in[4];
    const float* noise  = (const float*)d_in[5];
    const int*   dimidx = (const int*)  d_in[7];

    float* out_param = (float*)d_out;
    int write_lp = (out_size >= (int)(2 * SZ)) ? 1 : 0;
    float* out_lp = out_param + SZ;

    const float4* noise4 = (const float4*)noise;
    float4* param4 = (float4*)out_param;
    float4* lp4    = (float4*)(write_lp ? out_lp : out_param);

    arma_precompute<<<256, 128>>>(m, s_raw, a_raw, dimidx);
    arma_a8<<<2, 256>>>();
    arma_pass1<<<SS * QTR, 128>>>(noise4, lp4, write_lp);
    arma_pass2<<<SS * QTR, 256>>>(noise4, param4);
}